// round 5
// baseline (speedup 1.0000x reference)
#include <cuda_runtime.h>
#include <cuda_bf16.h>
#include <cstdint>

#define T_TOKENS 16384
#define H_DIM    4096
#define N_EXP    64
#define CAP      320

__device__ __align__(16) int g_idx[2 * T_TOKENS];
__device__ __align__(16) int g_cnt[32 * N_EXP];
__device__ __align__(16) __nv_bfloat16 g_whi[N_EXP * H_DIM];
__device__ __align__(16) __nv_bfloat16 g_wlo[N_EXP * H_DIM];

// ---------------------------------------------------------------------------
// helpers
// ---------------------------------------------------------------------------
__device__ __forceinline__ uint32_t smem_to_u32(const void* p) {
    uint32_t a;
    asm("{ .reg .u64 t; cvta.to.shared.u64 t, %1; cvt.u32.u64 %0, t; }" : "=r"(a) : "l"(p));
    return a;
}

#define LDSM_X4(r0, r1, r2, r3, addr)                                          \
    asm volatile("ldmatrix.sync.aligned.m8n8.x4.shared.b16 {%0,%1,%2,%3}, [%4];" \
                 : "=r"(r0), "=r"(r1), "=r"(r2), "=r"(r3) : "r"(addr))

#define MMA16816(d, a0, a1, a2, a3, b0, b1)                                        \
    asm volatile(                                                                  \
        "mma.sync.aligned.m16n8k16.row.col.f32.bf16.bf16.f32 "                     \
        "{%0,%1,%2,%3}, {%4,%5,%6,%7}, {%8,%9}, {%0,%1,%2,%3};"                    \
        : "+f"((d)[0]), "+f"((d)[1]), "+f"((d)[2]), "+f"((d)[3])                   \
        : "r"(a0), "r"(a1), "r"(a2), "r"(a3), "r"(b0), "r"(b1))

__device__ __forceinline__ void cvt_split4(float4 f, uint32_t& h0, uint32_t& h1,
                                           uint32_t& l0, uint32_t& l1) {
    __nv_bfloat162 a = __floats2bfloat162_rn(f.x, f.y);
    __nv_bfloat162 b = __floats2bfloat162_rn(f.z, f.w);
    float r0 = f.x - __bfloat162float(a.x);
    float r1 = f.y - __bfloat162float(a.y);
    float r2 = f.z - __bfloat162float(b.x);
    float r3 = f.w - __bfloat162float(b.y);
    __nv_bfloat162 c = __floats2bfloat162_rn(r0, r1);
    __nv_bfloat162 d = __floats2bfloat162_rn(r2, r3);
    h0 = *(uint32_t*)&a; h1 = *(uint32_t*)&b;
    l0 = *(uint32_t*)&c; l1 = *(uint32_t*)&d;
}

// ---------------------------------------------------------------------------
// smem layout. Per buffer: Ahi[256x64 bf16, stride 144B]=36864, Alo=36864,
// Bhi[64x64, stride 144B]=9216, Blo=9216 -> 92160 bytes; x2 buffers = 184320.
// Epilogue C (256 x 66 fp32 = 67584B) reuses buffer 0.
// ---------------------------------------------------------------------------
#define SA_STRIDE 144
#define BUF_BYTES 92160
#define OFF_AHI(b) ((b) * BUF_BYTES + 0)
#define OFF_ALO(b) ((b) * BUF_BYTES + 36864)
#define OFF_BHI(b) ((b) * BUF_BYTES + 73728)
#define OFF_BLO(b) ((b) * BUF_BYTES + 82944)
#define SMEM_BYTES (2 * BUF_BYTES)
#define CS 66

#define NCHUNK 64   // K chunks of 64

// ---------------------------------------------------------------------------
// W pre-convert: fp32 -> bf16 hi + bf16 lo (one-time per launch, ~1-2 us)
// ---------------------------------------------------------------------------
__global__ __launch_bounds__(512)
void wconv_kernel(const float* __restrict__ W) {
    const int i = (blockIdx.x * 512 + threadIdx.x) * 8;   // 8 floats per thread
    float4 f0 = *(const float4*)(W + i);
    float4 f1 = *(const float4*)(W + i + 4);
    uint32_t h[4], l[4];
    cvt_split4(f0, h[0], h[1], l[0], l[1]);
    cvt_split4(f1, h[2], h[3], l[2], l[3]);
    *(uint4*)(g_whi + i) = *(uint4*)h;
    *(uint4*)(g_wlo + i) = *(uint4*)l;
}

// ---------------------------------------------------------------------------
// Fused GEMM (bf16 3-product split via mma.sync) + top-2 epilogue.
// CTA: 256 tokens x 64 experts, K=4096. 16 warps: 8 along M, 2 along N.
// ---------------------------------------------------------------------------
__global__ __launch_bounds__(512, 1)
void gemm_topk_kernel(const float* __restrict__ A,
                      float* __restrict__ logits,
                      float* __restrict__ wflat) {
    extern __shared__ char smem[];
    const uint32_t sb = smem_to_u32(smem);
    const int tid  = threadIdx.x;
    const int wid  = tid >> 5;
    const int lane = tid & 31;
    const int wm   = wid & 7;     // M warp: rows [wm*32, +32)
    const int wn   = wid >> 3;    // N warp: cols [wn*32, +32)
    const int block_m = blockIdx.x * 256;

    // global load coords
    const int a_row  = tid >> 1;     // 0..255
    const int a_half = tid & 1;      // 32-float half of 64-wide chunk
    const int b_row  = tid >> 3;     // 0..63
    const int b_o    = (tid & 7) * 8;  // 8 bf16 per thread

    const float* Abase = A + (size_t)(block_m + a_row) * H_DIM + a_half * 32;
    const __nv_bfloat16* Whi = g_whi + (size_t)b_row * H_DIM + b_o;
    const __nv_bfloat16* Wlo = g_wlo + (size_t)b_row * H_DIM + b_o;

    const uint32_t a_lds = (uint32_t)((wm * 32 + (lane & 15)) * SA_STRIDE + (lane >> 4) * 16);
    const uint32_t b_lds = (uint32_t)((wn * 32 + (lane & 7) + ((lane >> 4) & 1) * 8) * SA_STRIDE +
                                      ((lane >> 3) & 1) * 16);

    float acc[2][4][4];
    #pragma unroll
    for (int i = 0; i < 2; i++)
        #pragma unroll
        for (int j = 0; j < 4; j++)
            #pragma unroll
            for (int q = 0; q < 4; q++) acc[i][j][q] = 0.0f;

    float4 fA[8];
    uint4 bhv, blv;

    // ---- prologue: chunk 0 -> buffer 0 ----
    #pragma unroll
    for (int i = 0; i < 8; i++) fA[i] = ((const float4*)Abase)[i];
    bhv = *(const uint4*)Whi;
    blv = *(const uint4*)Wlo;
    {
        char* ah = smem + OFF_AHI(0) + a_row * SA_STRIDE + a_half * 64;
        char* al = smem + OFF_ALO(0) + a_row * SA_STRIDE + a_half * 64;
        #pragma unroll
        for (int i = 0; i < 4; i++) {
            uint32_t h[4], l[4];
            cvt_split4(fA[i * 2 + 0], h[0], h[1], l[0], l[1]);
            cvt_split4(fA[i * 2 + 1], h[2], h[3], l[2], l[3]);
            *(uint4*)(ah + i * 16) = *(uint4*)h;
            *(uint4*)(al + i * 16) = *(uint4*)l;
        }
        *(uint4*)(smem + OFF_BHI(0) + b_row * SA_STRIDE + b_o * 2) = bhv;
        *(uint4*)(smem + OFF_BLO(0) + b_row * SA_STRIDE + b_o * 2) = blv;
    }
    __syncthreads();

    for (int kc = 0; kc < NCHUNK; kc++) {
        const int b = kc & 1;
        const bool has_next = (kc + 1 < NCHUNK);

        if (has_next) {
            const float* ga = Abase + (kc + 1) * 64;
            #pragma unroll
            for (int i = 0; i < 8; i++) fA[i] = ((const float4*)ga)[i];
            bhv = *(const uint4*)(Whi + (kc + 1) * 64);
            blv = *(const uint4*)(Wlo + (kc + 1) * 64);
        }

        const uint32_t ahi_b = sb + OFF_AHI(b) + a_lds;
        const uint32_t alo_b = sb + OFF_ALO(b) + a_lds;
        const uint32_t bhi_b = sb + OFF_BHI(b) + b_lds;
        const uint32_t blo_b = sb + OFF_BLO(b) + b_lds;

        #pragma unroll
        for (int ks = 0; ks < 4; ks++) {
            const uint32_t kb = ks * 32;
            uint32_t ah[2][4], al[2][4], bh[2][4], bl[2][4];
            #pragma unroll
            for (int mi = 0; mi < 2; mi++) {
                LDSM_X4(ah[mi][0], ah[mi][1], ah[mi][2], ah[mi][3],
                        ahi_b + mi * 16 * SA_STRIDE + kb);
                LDSM_X4(al[mi][0], al[mi][1], al[mi][2], al[mi][3],
                        alo_b + mi * 16 * SA_STRIDE + kb);
            }
            #pragma unroll
            for (int nt = 0; nt < 2; nt++) {
                LDSM_X4(bh[nt][0], bh[nt][1], bh[nt][2], bh[nt][3],
                        bhi_b + nt * 16 * SA_STRIDE + kb);
                LDSM_X4(bl[nt][0], bl[nt][1], bl[nt][2], bl[nt][3],
                        blo_b + nt * 16 * SA_STRIDE + kb);
            }
            #pragma unroll
            for (int mi = 0; mi < 2; mi++) {
                #pragma unroll
                for (int nt = 0; nt < 2; nt++) {
                    MMA16816(acc[mi][nt * 2 + 0], ah[mi][0], ah[mi][1], ah[mi][2], ah[mi][3],
                             bh[nt][0], bh[nt][1]);
                    MMA16816(acc[mi][nt * 2 + 1], ah[mi][0], ah[mi][1], ah[mi][2], ah[mi][3],
                             bh[nt][2], bh[nt][3]);
                    MMA16816(acc[mi][nt * 2 + 0], ah[mi][0], ah[mi][1], ah[mi][2], ah[mi][3],
                             bl[nt][0], bl[nt][1]);
                    MMA16816(acc[mi][nt * 2 + 1], ah[mi][0], ah[mi][1], ah[mi][2], ah[mi][3],
                             bl[nt][2], bl[nt][3]);
                    MMA16816(acc[mi][nt * 2 + 0], al[mi][0], al[mi][1], al[mi][2], al[mi][3],
                             bh[nt][0], bh[nt][1]);
                    MMA16816(acc[mi][nt * 2 + 1], al[mi][0], al[mi][1], al[mi][2], al[mi][3],
                             bh[nt][2], bh[nt][3]);
                }
            }
        }

        if (has_next) {
            const int nb = b ^ 1;
            char* ah = smem + OFF_AHI(nb) + a_row * SA_STRIDE + a_half * 64;
            char* al = smem + OFF_ALO(nb) + a_row * SA_STRIDE + a_half * 64;
            #pragma unroll
            for (int i = 0; i < 4; i++) {
                uint32_t h[4], l[4];
                cvt_split4(fA[i * 2 + 0], h[0], h[1], l[0], l[1]);
                cvt_split4(fA[i * 2 + 1], h[2], h[3], l[2], l[3]);
                *(uint4*)(ah + i * 16) = *(uint4*)h;
                *(uint4*)(al + i * 16) = *(uint4*)l;
            }
            *(uint4*)(smem + OFF_BHI(nb) + b_row * SA_STRIDE + b_o * 2) = bhv;
            *(uint4*)(smem + OFF_BLO(nb) + b_row * SA_STRIDE + b_o * 2) = blv;
            __syncthreads();
        }
    }

    // ---- epilogue ----
    __syncthreads();
    float* Cs = (float*)smem;
    #pragma unroll
    for (int mi = 0; mi < 2; mi++) {
        #pragma unroll
        for (int ni = 0; ni < 4; ni++) {
            int r0 = wm * 32 + mi * 16 + (lane >> 2);
            int c  = wn * 32 + ni * 8 + (lane & 3) * 2;
            *(float2*)(Cs + r0 * CS + c)       = make_float2(acc[mi][ni][0], acc[mi][ni][1]);
            *(float2*)(Cs + (r0 + 8) * CS + c) = make_float2(acc[mi][ni][2], acc[mi][ni][3]);
        }
    }
    __syncthreads();

    {   // logits: each thread writes half a row (32 floats)
        const int r = tid >> 1;
        const int cb = (tid & 1) * 32;
        float* lrow = logits + (size_t)(block_m + r) * N_EXP + cb;
        const float* src = Cs + r * CS + cb;
        #pragma unroll
        for (int i = 0; i < 8; i++) {
            float2 u = *(const float2*)(src + i * 4);
            float2 v = *(const float2*)(src + i * 4 + 2);
            *(float4*)(lrow + i * 4) = make_float4(u.x, u.y, v.x, v.y);
        }
    }

    if (tid < 256) {   // top-2 + renorm, one row per thread
        const float* row = Cs + tid * CS;
        float m1 = -3.4e38f, m2 = -3.4e38f;
        int i1 = 0, i2 = 0;
        #pragma unroll
        for (int e = 0; e < 64; e++) {
            float v = row[e];
            if (v > m1)      { m2 = m1; i2 = i1; m1 = v; i1 = e; }
            else if (v > m2) { m2 = v; i2 = e; }
        }
        const int t = block_m + tid;
        float w1 = 1.0f / (1.0f + expf(m2 - m1));
        wflat[t * 2 + 0] = w1;
        wflat[t * 2 + 1] = 1.0f - w1;
        g_idx[t]            = i1;
        g_idx[T_TOKENS + t] = i2;
    }
}

// ---------------------------------------------------------------------------
// Phase 1: per-tile (1024 entries) expert histogram -> g_cnt[tile][expert]
// ---------------------------------------------------------------------------
__global__ __launch_bounds__(256)
void hist_kernel() {
    __shared__ int hist[N_EXP];
    const int t = blockIdx.x;
    const int tid = threadIdx.x;
    if (tid < N_EXP) hist[tid] = 0;
    __syncthreads();
    int4 v = ((const int4*)g_idx)[t * 256 + tid];
    atomicAdd(&hist[v.x], 1);
    atomicAdd(&hist[v.y], 1);
    atomicAdd(&hist[v.z], 1);
    atomicAdd(&hist[v.w], 1);
    __syncthreads();
    if (tid < N_EXP) g_cnt[t * N_EXP + tid] = hist[tid];
}

// ---------------------------------------------------------------------------
// Phase 2: one block per expert, all 32 tiles processed in parallel (8 warps).
// base[t] = prefix of per-tile counts; within a tile, lane-blocked warp scan.
// ---------------------------------------------------------------------------
__global__ __launch_bounds__(256)
void assign_kernel(const float* __restrict__ wflat,
                   float* __restrict__ out_idx,
                   float* __restrict__ out_w) {
    const int e = blockIdx.x;
    const int tid = threadIdx.x;
    const int lane = tid & 31, w = tid >> 5;

    for (int i = tid; i < CAP; i += 256) {
        out_idx[e * CAP + i] = 0.0f;
        out_w[e * CAP + i]   = 0.0f;
    }

    __shared__ int sbase[32];
    if (tid < 32) {
        int c = g_cnt[tid * N_EXP + e];
        int inc = c;
        #pragma unroll
        for (int off = 1; off < 32; off <<= 1) {
            int n = __shfl_up_sync(0xffffffffu, inc, off);
            if (lane >= off) inc += n;
        }
        sbase[tid] = inc - c;   // exclusive prefix
    }
    __syncthreads();

    #pragma unroll
    for (int ti = 0; ti < 4; ti++) {
        const int t = w + ti * 8;
        // lane-blocked: lane handles entries [t*1024 + lane*32, +32)
        const int4* p = (const int4*)g_idx + t * 256 + lane * 8;
        int4 v[8];
        #pragma unroll
        for (int j = 0; j < 8; j++) v[j] = p[j];

        int cnt = 0;
        #pragma unroll
        for (int j = 0; j < 8; j++)
            cnt += (v[j].x == e) + (v[j].y == e) + (v[j].z == e) + (v[j].w == e);

        int inc = cnt;
        #pragma unroll
        for (int off = 1; off < 32; off <<= 1) {
            int n = __shfl_up_sync(0xffffffffu, inc, off);
            if (lane >= off) inc += n;
        }
        int pos = sbase[t] + inc - cnt;

        if (cnt) {
            const int a0 = t * 1024 + lane * 32;
            #pragma unroll
            for (int j = 0; j < 8; j++) {
                int comp[4] = {v[j].x, v[j].y, v[j].z, v[j].w};
                #pragma unroll
                for (int q = 0; q < 4; q++) {
                    if (comp[q] == e) {
                        if (pos < CAP) {
                            int a = a0 + j * 4 + q;
                            int token = a & (T_TOKENS - 1);
                            int slot  = a >> 14;
                            out_idx[e * CAP + pos] = (float)token;
                            out_w[e * CAP + pos]   = wflat[token * 2 + slot];
                        }
                        pos++;
                    }
                }
            }
        }
    }
}

// ---------------------------------------------------------------------------
// Output layout (float32): [idx E*CAP | w E*CAP | wflat T*2 | logits T*E]
// ---------------------------------------------------------------------------
extern "C" void kernel_launch(void* const* d_in, const int* in_sizes, int n_in,
                              void* d_out, int out_size) {
    const float* hs;
    const float* wr;
    if (in_sizes[0] == N_EXP * H_DIM) {
        wr = (const float*)d_in[0];
        hs = (const float*)d_in[1];
    } else {
        hs = (const float*)d_in[0];
        wr = (const float*)d_in[1];
    }

    float* out     = (float*)d_out;
    float* out_idx = out;
    float* out_w   = out + N_EXP * CAP;
    float* wflat   = out + 2 * N_EXP * CAP;
    float* logits  = out + 2 * N_EXP * CAP + 2 * T_TOKENS;

    wconv_kernel<<<(N_EXP * H_DIM) / (512 * 8), 512>>>(wr);
    cudaFuncSetAttribute(gemm_topk_kernel, cudaFuncAttributeMaxDynamicSharedMemorySize,
                         SMEM_BYTES);
    gemm_topk_kernel<<<T_TOKENS / 256, 512, SMEM_BYTES>>>(hs, logits, wflat);
    hist_kernel<<<32, 256>>>();
    assign_kernel<<<N_EXP, 256>>>(wflat, out_idx, out_w);
}

// round 6
// speedup vs baseline: 2.2279x; 2.2279x over previous
#include <cuda_runtime.h>
#include <cuda_bf16.h>
#include <cstdint>

#define T_TOKENS 16384
#define H_DIM    4096
#define N_EXP    64
#define CAP      320

__device__ __align__(16) int g_idx[2 * T_TOKENS];
__device__ __align__(16) int g_cnt[32 * N_EXP];
__device__ __align__(16) __nv_bfloat16 g_whi[N_EXP * H_DIM];
__device__ __align__(16) __nv_bfloat16 g_wlo[N_EXP * H_DIM];

// ---------------------------------------------------------------------------
// helpers
// ---------------------------------------------------------------------------
__device__ __forceinline__ uint32_t smem_to_u32(const void* p) {
    uint32_t a;
    asm("{ .reg .u64 t; cvta.to.shared.u64 t, %1; cvt.u32.u64 %0, t; }" : "=r"(a) : "l"(p));
    return a;
}

#define LDSM_X4(r0, r1, r2, r3, addr)                                          \
    asm volatile("ldmatrix.sync.aligned.m8n8.x4.shared.b16 {%0,%1,%2,%3}, [%4];" \
                 : "=r"(r0), "=r"(r1), "=r"(r2), "=r"(r3) : "r"(addr))

#define MMA16816(d, a0, a1, a2, a3, b0, b1)                                        \
    asm volatile(                                                                  \
        "mma.sync.aligned.m16n8k16.row.col.f32.bf16.bf16.f32 "                     \
        "{%0,%1,%2,%3}, {%4,%5,%6,%7}, {%8,%9}, {%0,%1,%2,%3};"                    \
        : "+f"((d)[0]), "+f"((d)[1]), "+f"((d)[2]), "+f"((d)[3])                   \
        : "r"(a0), "r"(a1), "r"(a2), "r"(a3), "r"(b0), "r"(b1))

__device__ __forceinline__ void cvt_split4(float4 f, uint32_t& h0, uint32_t& h1,
                                           uint32_t& l0, uint32_t& l1) {
    __nv_bfloat162 a = __floats2bfloat162_rn(f.x, f.y);
    __nv_bfloat162 b = __floats2bfloat162_rn(f.z, f.w);
    float r0 = f.x - __bfloat162float(a.x);
    float r1 = f.y - __bfloat162float(a.y);
    float r2 = f.z - __bfloat162float(b.x);
    float r3 = f.w - __bfloat162float(b.y);
    __nv_bfloat162 c = __floats2bfloat162_rn(r0, r1);
    __nv_bfloat162 d = __floats2bfloat162_rn(r2, r3);
    h0 = *(uint32_t*)&a; h1 = *(uint32_t*)&b;
    l0 = *(uint32_t*)&c; l1 = *(uint32_t*)&d;
}

// ---------------------------------------------------------------------------
// smem: per buffer Ahi[128x64 bf16, stride 144B]=18432, Alo=18432,
// Bhi[64x64]=9216, Blo=9216 -> 55296; x2 = 110592 bytes.
// Epilogue C (128 x 66 fp32 = 33792B) reuses buffer 0.
// ---------------------------------------------------------------------------
#define SA_STRIDE 144
#define BUF_BYTES 55296
#define OFF_AHI(b) ((b) * BUF_BYTES + 0)
#define OFF_ALO(b) ((b) * BUF_BYTES + 18432)
#define OFF_BHI(b) ((b) * BUF_BYTES + 36864)
#define OFF_BLO(b) ((b) * BUF_BYTES + 46080)
#define SMEM_BYTES (2 * BUF_BYTES)
#define CS 66

#define NCHUNK 64

// ---------------------------------------------------------------------------
// W pre-convert: fp32 -> bf16 hi + lo
// ---------------------------------------------------------------------------
__global__ __launch_bounds__(512)
void wconv_kernel(const float* __restrict__ W) {
    const int i = (blockIdx.x * 512 + threadIdx.x) * 8;
    float4 f0 = *(const float4*)(W + i);
    float4 f1 = *(const float4*)(W + i + 4);
    uint32_t h[4], l[4];
    cvt_split4(f0, h[0], h[1], l[0], l[1]);
    cvt_split4(f1, h[2], h[3], l[2], l[3]);
    *(uint4*)(g_whi + i) = *(uint4*)h;
    *(uint4*)(g_wlo + i) = *(uint4*)l;
}

// ---------------------------------------------------------------------------
// Fused GEMM (bf16 3-product split) + top-2 epilogue.
// CTA: 128 tokens x 64 experts, K=4096. 512 threads, 16 warps: 4 M x 4 N.
// ---------------------------------------------------------------------------
__global__ __launch_bounds__(512, 1)
void gemm_topk_kernel(const float* __restrict__ A,
                      float* __restrict__ logits,
                      float* __restrict__ wflat) {
    extern __shared__ char smem[];
    const uint32_t sb = smem_to_u32(smem);
    const int tid  = threadIdx.x;
    const int wid  = tid >> 5;
    const int lane = tid & 31;
    const int wm   = wid & 3;     // rows [wm*32, +32)
    const int wn   = wid >> 2;    // cols [wn*16, +16)
    const int block_m = blockIdx.x * 128;

    // global load coords
    const int a_row = tid >> 2;        // 0..127
    const int a_q   = tid & 3;         // 16-float quarter of 64-wide chunk
    const int b_row = tid >> 3;        // 0..63
    const int b_o   = (tid & 7) * 8;   // 8 bf16

    const float* Abase = A + (size_t)(block_m + a_row) * H_DIM + a_q * 16;
    const __nv_bfloat16* Whi = g_whi + (size_t)b_row * H_DIM + b_o;
    const __nv_bfloat16* Wlo = g_wlo + (size_t)b_row * H_DIM + b_o;

    const uint32_t a_lds = (uint32_t)((wm * 32 + (lane & 15)) * SA_STRIDE + (lane >> 4) * 16);
    const uint32_t b_lds = (uint32_t)((wn * 16 + (lane & 7) + ((lane >> 4) & 1) * 8) * SA_STRIDE +
                                      ((lane >> 3) & 1) * 16);

    float acc[2][2][4];
    #pragma unroll
    for (int i = 0; i < 2; i++)
        #pragma unroll
        for (int j = 0; j < 2; j++)
            #pragma unroll
            for (int q = 0; q < 4; q++) acc[i][j][q] = 0.0f;

    float4 fA[4];
    uint4 bhv, blv;

    // ---- prologue: chunk 0 -> buffer 0 ----
    #pragma unroll
    for (int i = 0; i < 4; i++) fA[i] = ((const float4*)Abase)[i];
    bhv = *(const uint4*)Whi;
    blv = *(const uint4*)Wlo;
    {
        char* ah = smem + OFF_AHI(0) + a_row * SA_STRIDE + a_q * 32;
        char* al = smem + OFF_ALO(0) + a_row * SA_STRIDE + a_q * 32;
        uint32_t h[8], l[8];
        cvt_split4(fA[0], h[0], h[1], l[0], l[1]);
        cvt_split4(fA[1], h[2], h[3], l[2], l[3]);
        cvt_split4(fA[2], h[4], h[5], l[4], l[5]);
        cvt_split4(fA[3], h[6], h[7], l[6], l[7]);
        *(uint4*)(ah)      = *(uint4*)&h[0];
        *(uint4*)(ah + 16) = *(uint4*)&h[4];
        *(uint4*)(al)      = *(uint4*)&l[0];
        *(uint4*)(al + 16) = *(uint4*)&l[4];
        *(uint4*)(smem + OFF_BHI(0) + b_row * SA_STRIDE + b_o * 2) = bhv;
        *(uint4*)(smem + OFF_BLO(0) + b_row * SA_STRIDE + b_o * 2) = blv;
    }
    __syncthreads();

    for (int kc = 0; kc < NCHUNK; kc++) {
        const int b = kc & 1;
        const bool has_next = (kc + 1 < NCHUNK);

        if (has_next) {
            const float* ga = Abase + (kc + 1) * 64;
            #pragma unroll
            for (int i = 0; i < 4; i++) fA[i] = ((const float4*)ga)[i];
            bhv = *(const uint4*)(Whi + (kc + 1) * 64);
            blv = *(const uint4*)(Wlo + (kc + 1) * 64);
        }

        const uint32_t ahi_b = sb + OFF_AHI(b) + a_lds;
        const uint32_t alo_b = sb + OFF_ALO(b) + a_lds;
        const uint32_t bhi_b = sb + OFF_BHI(b) + b_lds;
        const uint32_t blo_b = sb + OFF_BLO(b) + b_lds;

        #pragma unroll
        for (int ks = 0; ks < 4; ks++) {
            const uint32_t kb = ks * 32;
            uint32_t ah[2][4], al[2][4], bh[4], bl[4];
            #pragma unroll
            for (int mi = 0; mi < 2; mi++) {
                LDSM_X4(ah[mi][0], ah[mi][1], ah[mi][2], ah[mi][3],
                        ahi_b + mi * 16 * SA_STRIDE + kb);
                LDSM_X4(al[mi][0], al[mi][1], al[mi][2], al[mi][3],
                        alo_b + mi * 16 * SA_STRIDE + kb);
            }
            LDSM_X4(bh[0], bh[1], bh[2], bh[3], bhi_b + kb);
            LDSM_X4(bl[0], bl[1], bl[2], bl[3], blo_b + kb);

            #pragma unroll
            for (int mi = 0; mi < 2; mi++) {
                MMA16816(acc[mi][0], ah[mi][0], ah[mi][1], ah[mi][2], ah[mi][3], bh[0], bh[1]);
                MMA16816(acc[mi][1], ah[mi][0], ah[mi][1], ah[mi][2], ah[mi][3], bh[2], bh[3]);
                MMA16816(acc[mi][0], ah[mi][0], ah[mi][1], ah[mi][2], ah[mi][3], bl[0], bl[1]);
                MMA16816(acc[mi][1], ah[mi][0], ah[mi][1], ah[mi][2], ah[mi][3], bl[2], bl[3]);
                MMA16816(acc[mi][0], al[mi][0], al[mi][1], al[mi][2], al[mi][3], bh[0], bh[1]);
                MMA16816(acc[mi][1], al[mi][0], al[mi][1], al[mi][2], al[mi][3], bh[2], bh[3]);
            }
        }

        if (has_next) {
            const int nb = b ^ 1;
            char* ah = smem + OFF_AHI(nb) + a_row * SA_STRIDE + a_q * 32;
            char* al = smem + OFF_ALO(nb) + a_row * SA_STRIDE + a_q * 32;
            uint32_t h[8], l[8];
            cvt_split4(fA[0], h[0], h[1], l[0], l[1]);
            cvt_split4(fA[1], h[2], h[3], l[2], l[3]);
            cvt_split4(fA[2], h[4], h[5], l[4], l[5]);
            cvt_split4(fA[3], h[6], h[7], l[6], l[7]);
            *(uint4*)(ah)      = *(uint4*)&h[0];
            *(uint4*)(ah + 16) = *(uint4*)&h[4];
            *(uint4*)(al)      = *(uint4*)&l[0];
            *(uint4*)(al + 16) = *(uint4*)&l[4];
            *(uint4*)(smem + OFF_BHI(nb) + b_row * SA_STRIDE + b_o * 2) = bhv;
            *(uint4*)(smem + OFF_BLO(nb) + b_row * SA_STRIDE + b_o * 2) = blv;
            __syncthreads();
        }
    }

    // ---- epilogue: C -> smem (stride 66), fused top-2 ----
    float* Cs = (float*)smem;
    #pragma unroll
    for (int mi = 0; mi < 2; mi++) {
        #pragma unroll
        for (int ni = 0; ni < 2; ni++) {
            int r0 = wm * 32 + mi * 16 + (lane >> 2);
            int c  = wn * 16 + ni * 8 + (lane & 3) * 2;
            *(float2*)(Cs + r0 * CS + c)       = make_float2(acc[mi][ni][0], acc[mi][ni][1]);
            *(float2*)(Cs + (r0 + 8) * CS + c) = make_float2(acc[mi][ni][2], acc[mi][ni][3]);
        }
    }
    __syncthreads();

    {   // logits: each thread writes a 16-float quarter row
        const int r  = tid >> 2;
        const int cb = (tid & 3) * 16;
        float* lrow = logits + (size_t)(block_m + r) * N_EXP + cb;
        const float* src = Cs + r * CS + cb;
        #pragma unroll
        for (int i = 0; i < 4; i++) {
            float2 u = *(const float2*)(src + i * 4);
            float2 v = *(const float2*)(src + i * 4 + 2);
            *(float4*)(lrow + i * 4) = make_float4(u.x, u.y, v.x, v.y);
        }
    }

    if (tid < 128) {   // top-2 + renorm, one row per thread
        const float* row = Cs + tid * CS;
        float m1 = -3.4e38f, m2 = -3.4e38f;
        int i1 = 0, i2 = 0;
        #pragma unroll
        for (int e = 0; e < 64; e++) {
            float v = row[e];
            if (v > m1)      { m2 = m1; i2 = i1; m1 = v; i1 = e; }
            else if (v > m2) { m2 = v; i2 = e; }
        }
        const int t = block_m + tid;
        float w1 = 1.0f / (1.0f + expf(m2 - m1));
        wflat[t * 2 + 0] = w1;
        wflat[t * 2 + 1] = 1.0f - w1;
        g_idx[t]            = i1;
        g_idx[T_TOKENS + t] = i2;
    }
}

// ---------------------------------------------------------------------------
// Phase 1: per-tile (1024 entries) expert histogram
// ---------------------------------------------------------------------------
__global__ __launch_bounds__(256)
void hist_kernel() {
    __shared__ int hist[N_EXP];
    const int t = blockIdx.x;
    const int tid = threadIdx.x;
    if (tid < N_EXP) hist[tid] = 0;
    __syncthreads();
    int4 v = ((const int4*)g_idx)[t * 256 + tid];
    atomicAdd(&hist[v.x], 1);
    atomicAdd(&hist[v.y], 1);
    atomicAdd(&hist[v.z], 1);
    atomicAdd(&hist[v.w], 1);
    __syncthreads();
    if (tid < N_EXP) g_cnt[t * N_EXP + tid] = hist[tid];
}

// ---------------------------------------------------------------------------
// Phase 2: grid (64 experts, 4 tile-groups) x 256 threads. Each warp handles
// one tile: re-derives per-tile base via a 32-lane scan of g_cnt, then
// lane-blocked rank + scatter. Block y==0 warp 0 zeros the tail [total, CAP).
// ---------------------------------------------------------------------------
__global__ __launch_bounds__(256)
void assign_kernel(const float* __restrict__ wflat,
                   float* __restrict__ out_idx,
                   float* __restrict__ out_w) {
    const int e   = blockIdx.x;
    const int tid = threadIdx.x;
    const int lane = tid & 31, w = tid >> 5;
    const int t = blockIdx.y * 8 + w;       // tile 0..31

    // per-warp scan over the 32 tile counts for expert e
    int c = g_cnt[lane * N_EXP + e];
    int incl = c;
    #pragma unroll
    for (int off = 1; off < 32; off <<= 1) {
        int n = __shfl_up_sync(0xffffffffu, incl, off);
        if (lane >= off) incl += n;
    }
    const int base_t = __shfl_sync(0xffffffffu, incl, t) - __shfl_sync(0xffffffffu, c, t);
    const int total  = __shfl_sync(0xffffffffu, incl, 31);

    if (blockIdx.y == 0 && w == 0) {        // zero only the unwritten tail
        for (int i = total + lane; i < CAP; i += 32) {
            out_idx[e * CAP + i] = 0.0f;
            out_w[e * CAP + i]   = 0.0f;
        }
    }

    // lane-blocked: lane handles entries [t*1024 + lane*32, +32)
    const int4* p = (const int4*)g_idx + t * 256 + lane * 8;
    int4 v[8];
    #pragma unroll
    for (int j = 0; j < 8; j++) v[j] = p[j];

    int cnt = 0;
    #pragma unroll
    for (int j = 0; j < 8; j++)
        cnt += (v[j].x == e) + (v[j].y == e) + (v[j].z == e) + (v[j].w == e);

    int inc = cnt;
    #pragma unroll
    for (int off = 1; off < 32; off <<= 1) {
        int n = __shfl_up_sync(0xffffffffu, inc, off);
        if (lane >= off) inc += n;
    }
    int pos = base_t + inc - cnt;

    if (cnt) {
        const int a0 = t * 1024 + lane * 32;
        #pragma unroll
        for (int j = 0; j < 8; j++) {
            int comp[4] = {v[j].x, v[j].y, v[j].z, v[j].w};
            #pragma unroll
            for (int q = 0; q < 4; q++) {
                if (comp[q] == e) {
                    if (pos < CAP) {
                        int a = a0 + j * 4 + q;
                        int token = a & (T_TOKENS - 1);
                        int slot  = a >> 14;
                        out_idx[e * CAP + pos] = (float)token;
                        out_w[e * CAP + pos]   = wflat[token * 2 + slot];
                    }
                    pos++;
                }
            }
        }
    }
}

// ---------------------------------------------------------------------------
// Output layout (float32): [idx E*CAP | w E*CAP | wflat T*2 | logits T*E]
// ---------------------------------------------------------------------------
extern "C" void kernel_launch(void* const* d_in, const int* in_sizes, int n_in,
                              void* d_out, int out_size) {
    const float* hs;
    const float* wr;
    if (in_sizes[0] == N_EXP * H_DIM) {
        wr = (const float*)d_in[0];
        hs = (const float*)d_in[1];
    } else {
        hs = (const float*)d_in[0];
        wr = (const float*)d_in[1];
    }

    float* out     = (float*)d_out;
    float* out_idx = out;
    float* out_w   = out + N_EXP * CAP;
    float* wflat   = out + 2 * N_EXP * CAP;
    float* logits  = out + 2 * N_EXP * CAP + 2 * T_TOKENS;

    wconv_kernel<<<(N_EXP * H_DIM) / (512 * 8), 512>>>(wr);
    cudaFuncSetAttribute(gemm_topk_kernel, cudaFuncAttributeMaxDynamicSharedMemorySize,
                         SMEM_BYTES);
    gemm_topk_kernel<<<T_TOKENS / 128, 512, SMEM_BYTES>>>(hs, logits, wflat);
    hist_kernel<<<32, 256>>>();
    assign_kernel<<<dim3(N_EXP, 4), 256>>>(wflat, out_idx, out_w);
}